// round 8
// baseline (speedup 1.0000x reference)
#include <cuda_runtime.h>
#include <math.h>
#include <stdint.h>

// ---------------- problem constants ----------------
#define Bn 2
#define Hn 8
#define Ln 4096
#define Dm 512
#define dh 64
#define NBH (Bn*Hn)       // 16
#define SMAX 64           // upper bound on n_top (actual 45)

// ---------------- device scratch (no allocs allowed) ----------------
__device__ __align__(256) float g_q[(size_t)NBH*Ln*dh];   // [bh][l][d]
__device__ __align__(256) float g_k[(size_t)NBH*Ln*dh];
__device__ __align__(256) float g_v[(size_t)NBH*Ln*dh];
__device__ __align__(256) float g_m[(size_t)NBH*Ln];
__device__ int   g_top[NBH*SMAX];
__device__ __align__(256) float g_tot[(size_t)NBH*64*dh]; // chunk totals for cumsum

// ---------------- tf32 helpers (family-portable PTX, sm_80+) ----------------
__device__ __forceinline__ uint32_t f32_to_tf32(float x){
    uint32_t r; asm("cvt.rna.tf32.f32 %0, %1;" : "=r"(r) : "f"(x)); return r;
}

#define MMA_TF32(c, a, b0_, b1_) \
    asm volatile("mma.sync.aligned.m16n8k8.row.col.f32.tf32.tf32.f32 " \
        "{%0,%1,%2,%3}, {%4,%5,%6,%7}, {%8,%9}, {%0,%1,%2,%3};" \
        : "+f"((c)[0]), "+f"((c)[1]), "+f"((c)[2]), "+f"((c)[3]) \
        : "r"((a)[0]), "r"((a)[1]), "r"((a)[2]), "r"((a)[3]), \
          "r"(b0_), "r"(b1_))

// ---------------- K1: 3xTF32 projection GEMM ----------------
// out[bh][l][d] = X @ W + bias.  X:[8192,512] rm, W:[512,512] rm.
// A (X tile) and B (W tile) split into tf32 hi/lo in-kernel; 3 mma passes.
#define PA 36          // padded A row stride (floats): banks (4r+c)%32 distinct
#define PB 136         // padded B row stride (floats): banks (8k+n)%32 distinct
#define SMEM_FLOATS (2*128*PA + 2*32*PB)     // 9216 + 8704 = 17920
#define SMEM_BYTES  (SMEM_FLOATS*4)          // 71680

__global__ __launch_bounds__(256, 2)
void proj_mma(const float* __restrict__ X, const float* __restrict__ W,
              const float* __restrict__ bias, float* __restrict__ out)
{
    extern __shared__ float smf[];
    float* Ah = smf;
    float* Al = smf + 128*PA;
    float* Bh = smf + 2*128*PA;
    float* Bl = Bh + 32*PB;

    const int tid  = threadIdx.x;
    const int lane = tid & 31, warp = tid >> 5;
    const int wm = warp & 3, wn = warp >> 2;          // warp tile: 32m x 64n
    const int rowBase = blockIdx.y * 128;
    const int colBase = blockIdx.x * 128;

    const int lg = lane >> 2;        // group id 0..7
    const int lt = lane & 3;         // thread-in-group 0..3

    float acc[2][8][4];
    #pragma unroll
    for (int mt = 0; mt < 2; mt++)
        #pragma unroll
        for (int nt = 0; nt < 8; nt++)
            #pragma unroll
            for (int j = 0; j < 4; j++) acc[mt][nt][j] = 0.f;

    // per-thread gmem load coords (16 consecutive floats each)
    const int am = tid >> 1, ak = (tid & 1) * 16;     // A: 128 rows x 32 k
    const int bk = tid >> 3, bn = (tid & 7) * 16;     // B: 32 rows x 128 n

    for (int kc = 0; kc < Dm; kc += 32) {
        // issue gmem loads first (latency overlaps the barrier)
        const float4* ga = (const float4*)(X + (size_t)(rowBase + am) * Dm + kc + ak);
        const float4* gb = (const float4*)(W + (size_t)(kc + bk) * Dm + colBase + bn);
        float4 av[4], bv[4];
        #pragma unroll
        for (int i = 0; i < 4; i++) av[i] = ga[i];
        #pragma unroll
        for (int i = 0; i < 4; i++) bv[i] = gb[i];

        __syncthreads();   // previous chunk's compute done

        #pragma unroll
        for (int i = 0; i < 4; i++) {
            float xs[4] = {av[i].x, av[i].y, av[i].z, av[i].w};
            float ys[4] = {bv[i].x, bv[i].y, bv[i].z, bv[i].w};
            #pragma unroll
            for (int j = 0; j < 4; j++) {
                uint32_t h = f32_to_tf32(xs[j]);
                float hf = __uint_as_float(h);
                Ah[am*PA + ak + i*4 + j] = hf;
                Al[am*PA + ak + i*4 + j] =
                    __uint_as_float(f32_to_tf32(xs[j] - hf));
                uint32_t g = f32_to_tf32(ys[j]);
                float gf = __uint_as_float(g);
                Bh[bk*PB + bn + i*4 + j] = gf;
                Bl[bk*PB + bn + i*4 + j] =
                    __uint_as_float(f32_to_tf32(ys[j] - gf));
            }
        }
        __syncthreads();

        // ---- compute: 4 k8-steps ----
        #pragma unroll
        for (int ks = 0; ks < 4; ks++) {
            const int c = ks*8 + lt;
            uint32_t ah[2][4], al[2][4];
            #pragma unroll
            for (int mt = 0; mt < 2; mt++) {
                int r = wm*32 + mt*16 + lg;
                ah[mt][0] = __float_as_uint(Ah[r*PA + c]);
                ah[mt][1] = __float_as_uint(Ah[(r+8)*PA + c]);
                ah[mt][2] = __float_as_uint(Ah[r*PA + c + 4]);
                ah[mt][3] = __float_as_uint(Ah[(r+8)*PA + c + 4]);
                al[mt][0] = __float_as_uint(Al[r*PA + c]);
                al[mt][1] = __float_as_uint(Al[(r+8)*PA + c]);
                al[mt][2] = __float_as_uint(Al[r*PA + c + 4]);
                al[mt][3] = __float_as_uint(Al[(r+8)*PA + c + 4]);
            }
            #pragma unroll
            for (int nt = 0; nt < 8; nt++) {
                int n = wn*64 + nt*8 + lg;
                int kk = ks*8 + lt;
                uint32_t bh0 = __float_as_uint(Bh[kk*PB + n]);
                uint32_t bh1 = __float_as_uint(Bh[(kk+4)*PB + n]);
                uint32_t bl0 = __float_as_uint(Bl[kk*PB + n]);
                uint32_t bl1 = __float_as_uint(Bl[(kk+4)*PB + n]);
                #pragma unroll
                for (int mt = 0; mt < 2; mt++) {
                    MMA_TF32(acc[mt][nt], ah[mt], bh0, bh1);
                    MMA_TF32(acc[mt][nt], ah[mt], bl0, bl1);
                    MMA_TF32(acc[mt][nt], al[mt], bh0, bh1);
                }
            }
        }
    }

    // ---- epilogue: add bias, scatter to [bh][l][d] layout ----
    #pragma unroll
    for (int mt = 0; mt < 2; mt++) {
        int r0 = rowBase + wm*32 + mt*16 + lg;
        #pragma unroll
        for (int nt = 0; nt < 8; nt++) {
            int col = colBase + wn*64 + nt*8 + lt*2;
            float b0 = bias[col], b1 = bias[col+1];
            int h = col >> 6, d = col & 63;
            #pragma unroll
            for (int rr = 0; rr < 2; rr++) {
                int m = r0 + rr*8;
                int b = m >> 12, l = m & (Ln - 1);
                float2 v;
                v.x = acc[mt][nt][rr*2+0] + b0;
                v.y = acc[mt][nt][rr*2+1] + b1;
                *(float2*)(out + (((size_t)(b * Hn + h) << 12 | l) << 6) + d) = v;
            }
        }
    }
}

// ---------------- K2: sampled scores -> m ----------------
__global__ __launch_bounds__(256)
void sample_score_kernel(const int* __restrict__ idxs, int S)
{
    int gid = blockIdx.x * 8 + (threadIdx.x >> 5);
    int lane = threadIdx.x & 31;
    int bh = gid >> 12;
    int l = gid & (Ln - 1);

    const float* q = g_q + ((size_t)bh << 18) + ((size_t)l << 6);
    float2 q2 = *(const float2*)(q + 2 * lane);
    const float* kb = g_k + ((size_t)bh << 18);

    float mx = -INFINITY, sm = 0.f;
    for (int s = 0; s < S; s++) {
        int idx = idxs[l * S + s];
        float2 k2 = *(const float2*)(kb + ((size_t)idx << 6) + 2 * lane);
        float p = q2.x * k2.x + q2.y * k2.y;
        #pragma unroll
        for (int o = 16; o; o >>= 1) p += __shfl_xor_sync(0xffffffffu, p, o);
        mx = fmaxf(mx, p);
        sm += p;
    }
    if (lane == 0)
        g_m[((size_t)bh << 12) + l] = mx - sm * (1.0f / (float)Ln);
}

// ---------------- K3: top-S argmax passes per (b,h) ----------------
__global__ __launch_bounds__(256)
void topk_kernel(int S)
{
    __shared__ float sm[Ln];
    __shared__ float rv[256];
    __shared__ int   ri[256];
    int bh = blockIdx.x, tid = threadIdx.x;

    for (int i = tid; i < Ln; i += 256) sm[i] = g_m[((size_t)bh << 12) + i];
    __syncthreads();

    for (int t = 0; t < S; t++) {
        float best = -INFINITY;
        int bi = Ln;
        for (int i = tid; i < Ln; i += 256) {
            float v = sm[i];
            if (v > best || (v == best && i < bi)) { best = v; bi = i; }
        }
        rv[tid] = best; ri[tid] = bi;
        __syncthreads();
        for (int o = 128; o; o >>= 1) {
            if (tid < o) {
                if (rv[tid + o] > rv[tid] ||
                    (rv[tid + o] == rv[tid] && ri[tid + o] < ri[tid])) {
                    rv[tid] = rv[tid + o]; ri[tid] = ri[tid + o];
                }
            }
            __syncthreads();
        }
        if (tid == 0) {
            g_top[bh * SMAX + t] = ri[0];
            sm[ri[0]] = -INFINITY;
        }
        __syncthreads();
    }
}

// ---------------- K5a: chunk-local cumsum of v (float4) ----------------
__global__ __launch_bounds__(128)
void cumsum_part(float* __restrict__ out)
{
    int tid = threadIdx.x;
    int c = blockIdx.x * 8 + (tid >> 4);   // chunk [0,64)
    int bh = blockIdx.y;
    int d4 = (tid & 15) * 4;
    int b = bh >> 3, h = bh & 7;
    const float* vb = g_v + ((size_t)bh << 18) + ((size_t)(c * 64) << 6) + d4;
    float* ob = out + ((size_t)(b * Ln + c * 64)) * Dm + h * 64 + d4;
    float4 run = make_float4(0.f, 0.f, 0.f, 0.f);
    #pragma unroll 8
    for (int i = 0; i < 64; i++) {
        float4 v = *(const float4*)(vb + ((size_t)i << 6));
        run.x += v.x; run.y += v.y; run.z += v.z; run.w += v.w;
        *(float4*)(ob + (size_t)i * Dm) = run;
    }
    *(float4*)&g_tot[((size_t)bh * 64 + c) * 64 + d4] = run;
}

// ---------------- K5b: exclusive scan of chunk totals ----------------
__global__ void cumsum_scan()
{
    int bh = blockIdx.x;
    int d4 = threadIdx.x * 4;   // 16 threads
    float4 run = make_float4(0.f, 0.f, 0.f, 0.f);
    for (int c = 0; c < 64; c++) {
        float4* p = (float4*)&g_tot[((size_t)bh * 64 + c) * 64 + d4];
        float4 t = *p;
        *p = run;
        run.x += t.x; run.y += t.y; run.z += t.z; run.w += t.w;
    }
}

// ---------------- K5c: add chunk offsets (float4) ----------------
__global__ __launch_bounds__(128)
void cumsum_add(float* __restrict__ out)
{
    int tid = threadIdx.x;
    int c = blockIdx.x * 8 + (tid >> 4);
    if (c == 0) return;
    int bh = blockIdx.y;
    int d4 = (tid & 15) * 4;
    float4 off = *(const float4*)&g_tot[((size_t)bh * 64 + c) * 64 + d4];
    int b = bh >> 3, h = bh & 7;
    float* ob = out + ((size_t)(b * Ln + c * 64)) * Dm + h * 64 + d4;
    #pragma unroll 8
    for (int i = 0; i < 64; i++) {
        float4 v = *(const float4*)(ob + (size_t)i * Dm);
        v.x += off.x; v.y += off.y; v.z += off.z; v.w += off.w;
        *(float4*)(ob + (size_t)i * Dm) = v;
    }
}

// ---------------- K4: full attention on selected rows + scatter ----------------
__global__ __launch_bounds__(256)
void attn_kernel(float* __restrict__ out, int S)
{
    __shared__ float qs[64];
    __shared__ float sc[Ln];
    __shared__ float red[256];
    __shared__ float vr[4][64];

    int bh = blockIdx.y, u = blockIdx.x;
    int tid = threadIdx.x;
    int lu = g_top[bh * SMAX + u];
    int nk = lu + 1;   // causal: keys 0..lu inclusive

    const float* qb = g_q + ((size_t)bh << 18) + ((size_t)lu << 6);
    if (tid < 64) qs[tid] = qb[tid];
    __syncthreads();

    int warp = tid >> 5, lane = tid & 31;
    const float* kb = g_k + ((size_t)bh << 18);
    float q0 = qs[2 * lane], q1 = qs[2 * lane + 1];
    const float scale = 0.125f;  // 1/sqrt(64)

    for (int key = warp; key < nk; key += 8) {
        float2 k2 = *(const float2*)(kb + ((size_t)key << 6) + 2 * lane);
        float p = q0 * k2.x + q1 * k2.y;
        #pragma unroll
        for (int o = 16; o; o >>= 1) p += __shfl_xor_sync(0xffffffffu, p, o);
        if (lane == 0) sc[key] = p * scale;
    }
    __syncthreads();

    float mx = -INFINITY;
    for (int i = tid; i < nk; i += 256) mx = fmaxf(mx, sc[i]);
    red[tid] = mx; __syncthreads();
    for (int o = 128; o; o >>= 1) {
        if (tid < o) red[tid] = fmaxf(red[tid], red[tid + o]);
        __syncthreads();
    }
    mx = red[0]; __syncthreads();

    float z = 0.f;
    for (int i = tid; i < nk; i += 256) {
        float e = __expf(sc[i] - mx);
        sc[i] = e;
        z += e;
    }
    red[tid] = z; __syncthreads();
    for (int o = 128; o; o >>= 1) {
        if (tid < o) red[tid] += red[tid + o];
        __syncthreads();
    }
    z = red[0]; __syncthreads();

    int g = tid >> 6, dl = tid & 63;
    const float* vb = g_v + ((size_t)bh << 18);
    float acc = 0.f;
    for (int key = g; key < nk; key += 4)
        acc += sc[key] * vb[((size_t)key << 6) + dl];
    vr[g][dl] = acc;
    __syncthreads();

    if (tid < 64) {
        float s = (vr[0][tid] + vr[1][tid]) + (vr[2][tid] + vr[3][tid]);
        int b = bh >> 3, h = bh & 7;
        out[((size_t)(b * Ln + lu)) * Dm + h * 64 + tid] = s / z;
    }
}

// ---------------- launch ----------------
extern "C" void kernel_launch(void* const* d_in, const int* in_sizes, int n_in,
                              void* d_out, int out_size)
{
    const float* queries = (const float*)d_in[0];
    const float* keys    = (const float*)d_in[1];
    const float* values  = (const float*)d_in[2];
    const float* Wq = (const float*)d_in[3];
    const float* bq = (const float*)d_in[4];
    const float* Wk = (const float*)d_in[5];
    const float* bk = (const float*)d_in[6];
    const float* Wv = (const float*)d_in[7];
    const float* bv = (const float*)d_in[8];
    const int*  idxs = (const int*)d_in[9];
    int S = in_sizes[9] / Ln;   // 45
    float* out = (float*)d_out;

    float *gq, *gk, *gv;
    cudaGetSymbolAddress((void**)&gq, g_q);
    cudaGetSymbolAddress((void**)&gk, g_k);
    cudaGetSymbolAddress((void**)&gv, g_v);

    cudaFuncSetAttribute(proj_mma, cudaFuncAttributeMaxDynamicSharedMemorySize,
                         SMEM_BYTES);

    dim3 gemmGrid(Dm / 128, (Bn * Ln) / 128);   // (4, 64)
    proj_mma<<<gemmGrid, 256, SMEM_BYTES>>>(queries, Wq, bq, gq);
    proj_mma<<<gemmGrid, 256, SMEM_BYTES>>>(keys,    Wk, bk, gk);
    proj_mma<<<gemmGrid, 256, SMEM_BYTES>>>(values,  Wv, bv, gv);

    // cumsum of v into out (final layout)
    cumsum_part<<<dim3(8, NBH), 128>>>(out);
    cumsum_scan<<<NBH, 16>>>();
    cumsum_add<<<dim3(8, NBH), 128>>>(out);

    // sparse-attention measurement + selection
    sample_score_kernel<<<(NBH * Ln) / 8, 256>>>(idxs, S);
    topk_kernel<<<NBH, 256>>>(S);

    // full attention on selected rows, scatter into out
    attn_kernel<<<dim3(S, NBH), 256>>>(out, S);
}

// round 9
// speedup vs baseline: 1.7367x; 1.7367x over previous
#include <cuda_runtime.h>
#include <math.h>
#include <stdint.h>

// ---------------- problem constants ----------------
#define Bn 2
#define Hn 8
#define Ln 4096
#define Dm 512
#define dh 64
#define NBH (Bn*Hn)       // 16
#define SMAX 64           // upper bound on n_top (actual 45)
#define NCH 128           // cumsum chunks per bh (32 rows each)

// ---------------- device scratch (no allocs allowed) ----------------
__device__ __align__(256) float g_q[(size_t)NBH*Ln*dh];   // [bh][l][d]
__device__ __align__(256) float g_k[(size_t)NBH*Ln*dh];
__device__ __align__(256) float g_v[(size_t)NBH*Ln*dh];
__device__ __align__(256) float g_m[(size_t)NBH*Ln];
__device__ int   g_top[NBH*SMAX];
__device__ __align__(256) float g_tot[(size_t)NBH*NCH*dh]; // chunk totals for cumsum

// ---------------- f32x2 helpers (Blackwell packed fp32) ----------------
__device__ __forceinline__ unsigned long long dup_f32(float x){
    unsigned long long r;
    asm("mov.b64 %0, {%1, %1};" : "=l"(r) : "f"(x));
    return r;
}
__device__ __forceinline__ unsigned long long ffma2(unsigned long long a,
                                                    unsigned long long b,
                                                    unsigned long long c){
    unsigned long long d;
    asm("fma.rn.f32x2 %0, %1, %2, %3;" : "=l"(d) : "l"(a), "l"(b), "l"(c));
    return d;
}
__device__ __forceinline__ float2 unpack2(unsigned long long v){
    float2 r;
    asm("mov.b64 {%0, %1}, %2;" : "=f"(r.x), "=f"(r.y) : "l"(v));
    return r;
}

// ---------------- K1: fp32 FFMA2 projection GEMM, double-buffered ----------------
// out[bh][l][d] = (X @ W + bias) reshaped; X:[B*L, D] rm, W:[D, D] rm.
#define BM 128
#define BN 128
#define BK 16
#define PA 132   // padded A row stride (floats); 132*4 % 16 == 0 (LDS.128 ok), 2-way store conflict

__global__ __launch_bounds__(256, 2)
void proj_kernel(const float* __restrict__ X, const float* __restrict__ W,
                 const float* __restrict__ bias, float* __restrict__ out)
{
    __shared__ __align__(16) float As[2][BK][PA];   // [stage][k][m]
    __shared__ __align__(16) float Bs[2][BK][BN];   // [stage][k][n]

    const int tid = threadIdx.x;
    const int tx = tid & 15, ty = tid >> 4;
    const int m0 = ty * 8, n0 = tx * 8;
    const int rowBase = blockIdx.y * BM;
    const int colBase = blockIdx.x * BN;

    // per-thread gmem load coords (each thread: 2 float4 from A, 2 from B)
    const int a_r  = tid >> 2;          // + t*64  -> row in tile [0,128)
    const int a_kq = (tid & 3) * 4;     // k quad
    const int b_r  = tid >> 5;          // + t*8   -> k row [0,16)
    const int b_cq = (tid & 31) * 4;    // col quad

    float4 a_stg[2], b_stg[2];

    // ---- prologue: load + store chunk 0 into stage 0 ----
    #pragma unroll
    for (int t = 0; t < 2; t++) {
        a_stg[t] = *(const float4*)(X + (size_t)(rowBase + a_r + t*64) * Dm + a_kq);
        b_stg[t] = *(const float4*)(W + (size_t)(b_r + t*8) * Dm + colBase + b_cq);
    }
    #pragma unroll
    for (int t = 0; t < 2; t++) {
        As[0][a_kq + 0][a_r + t*64] = a_stg[t].x;
        As[0][a_kq + 1][a_r + t*64] = a_stg[t].y;
        As[0][a_kq + 2][a_r + t*64] = a_stg[t].z;
        As[0][a_kq + 3][a_r + t*64] = a_stg[t].w;
        *(float4*)&Bs[0][b_r + t*8][b_cq] = b_stg[t];
    }
    __syncthreads();

    unsigned long long acc[4][8];
    #pragma unroll
    for (int i = 0; i < 4; i++)
        #pragma unroll
        for (int j = 0; j < 8; j++) acc[i][j] = 0ull;

    int s = 0;
    for (int kc = 0; kc < Dm; kc += BK) {
        const bool more = (kc + BK < Dm);
        // issue next chunk's gmem loads; latency hidden under compute
        if (more) {
            #pragma unroll
            for (int t = 0; t < 2; t++) {
                a_stg[t] = *(const float4*)(X + (size_t)(rowBase + a_r + t*64) * Dm + (kc + BK) + a_kq);
                b_stg[t] = *(const float4*)(W + (size_t)(kc + BK + b_r + t*8) * Dm + colBase + b_cq);
            }
        }

        // ---- compute from stage s ----
        #pragma unroll
        for (int k = 0; k < BK; k++) {
            ulonglong2 a01 = *(const ulonglong2*)&As[s][k][m0];
            ulonglong2 a23 = *(const ulonglong2*)(&As[s][k][m0] + 4);
            unsigned long long ap[4] = { a01.x, a01.y, a23.x, a23.y };
            float4 b0 = *(const float4*)&Bs[s][k][n0];
            float4 b1 = *(const float4*)(&Bs[s][k][n0] + 4);
            unsigned long long bd[8] = {
                dup_f32(b0.x), dup_f32(b0.y), dup_f32(b0.z), dup_f32(b0.w),
                dup_f32(b1.x), dup_f32(b1.y), dup_f32(b1.z), dup_f32(b1.w)
            };
            #pragma unroll
            for (int i = 0; i < 4; i++)
                #pragma unroll
                for (int j = 0; j < 8; j++)
                    acc[i][j] = ffma2(ap[i], bd[j], acc[i][j]);
        }

        // ---- store next chunk into the other stage ----
        if (more) {
            const int so = s ^ 1;
            #pragma unroll
            for (int t = 0; t < 2; t++) {
                As[so][a_kq + 0][a_r + t*64] = a_stg[t].x;
                As[so][a_kq + 1][a_r + t*64] = a_stg[t].y;
                As[so][a_kq + 2][a_r + t*64] = a_stg[t].z;
                As[so][a_kq + 3][a_r + t*64] = a_stg[t].w;
                *(float4*)&Bs[so][b_r + t*8][b_cq] = b_stg[t];
            }
            __syncthreads();
        }
        s ^= 1;
    }

    // ---- epilogue: add bias, scatter to [bh][l][d] layout ----
    float bvv[8];
    #pragma unroll
    for (int j = 0; j < 8; j++) bvv[j] = bias[colBase + n0 + j];

    const int c0 = colBase + n0;
    const int h = c0 >> 6;
    const int d0 = c0 & 63;

    #pragma unroll
    for (int i = 0; i < 4; i++) {
        #pragma unroll
        for (int rr = 0; rr < 2; rr++) {
            int r = rowBase + m0 + 2 * i + rr;
            int b = r >> 12;
            int l = r & (Ln - 1);
            float* o = out + (((size_t)(b * Hn + h) * Ln + l) << 6) + d0;
            float vals[8];
            #pragma unroll
            for (int j = 0; j < 8; j++) {
                float2 f2 = unpack2(acc[i][j]);
                vals[j] = (rr == 0 ? f2.x : f2.y) + bvv[j];
            }
            *(float4*)o       = make_float4(vals[0], vals[1], vals[2], vals[3]);
            *(float4*)(o + 4) = make_float4(vals[4], vals[5], vals[6], vals[7]);
        }
    }
}

// ---------------- K2: sampled scores -> m ----------------
__global__ __launch_bounds__(256)
void sample_score_kernel(const int* __restrict__ idxs, int S)
{
    int gid = blockIdx.x * 8 + (threadIdx.x >> 5);
    int lane = threadIdx.x & 31;
    int bh = gid >> 12;
    int l = gid & (Ln - 1);

    const float* q = g_q + ((size_t)bh << 18) + ((size_t)l << 6);
    float2 q2 = *(const float2*)(q + 2 * lane);
    const float* kb = g_k + ((size_t)bh << 18);

    float mx = -INFINITY, sm = 0.f;
    for (int s = 0; s < S; s++) {
        int idx = idxs[l * S + s];
        float2 k2 = *(const float2*)(kb + ((size_t)idx << 6) + 2 * lane);
        float p = q2.x * k2.x + q2.y * k2.y;
        #pragma unroll
        for (int o = 16; o; o >>= 1) p += __shfl_xor_sync(0xffffffffu, p, o);
        mx = fmaxf(mx, p);
        sm += p;
    }
    if (lane == 0)
        g_m[((size_t)bh << 12) + l] = mx - sm * (1.0f / (float)Ln);
}

// ---------------- K3: top-S argmax passes per (b,h) ----------------
__global__ __launch_bounds__(256)
void topk_kernel(int S)
{
    __shared__ float sm[Ln];
    __shared__ float rv[256];
    __shared__ int   ri[256];
    int bh = blockIdx.x, tid = threadIdx.x;

    for (int i = tid; i < Ln; i += 256) sm[i] = g_m[((size_t)bh << 12) + i];
    __syncthreads();

    for (int t = 0; t < S; t++) {
        float best = -INFINITY;
        int bi = Ln;
        for (int i = tid; i < Ln; i += 256) {
            float v = sm[i];
            if (v > best || (v == best && i < bi)) { best = v; bi = i; }
        }
        rv[tid] = best; ri[tid] = bi;
        __syncthreads();
        for (int o = 128; o; o >>= 1) {
            if (tid < o) {
                if (rv[tid + o] > rv[tid] ||
                    (rv[tid + o] == rv[tid] && ri[tid + o] < ri[tid])) {
                    rv[tid] = rv[tid + o]; ri[tid] = ri[tid + o];
                }
            }
            __syncthreads();
        }
        if (tid == 0) {
            g_top[bh * SMAX + t] = ri[0];
            sm[ri[0]] = -INFINITY;
        }
        __syncthreads();
    }
}

// ---------------- K5a: 32-row chunk-local cumsum of v (float4) ----------------
__global__ __launch_bounds__(128)
void cumsum_part(float* __restrict__ out)
{
    int tid = threadIdx.x;
    int c = blockIdx.x * 8 + (tid >> 4);   // chunk [0,128)
    int bh = blockIdx.y;
    int d4 = (tid & 15) * 4;
    int b = bh >> 3, h = bh & 7;
    const float* vb = g_v + ((size_t)bh << 18) + ((size_t)(c * 32) << 6) + d4;
    float* ob = out + ((size_t)(b * Ln + c * 32)) * Dm + h * 64 + d4;
    float4 run = make_float4(0.f, 0.f, 0.f, 0.f);
    #pragma unroll 8
    for (int i = 0; i < 32; i++) {
        float4 v = *(const float4*)(vb + ((size_t)i << 6));
        run.x += v.x; run.y += v.y; run.z += v.z; run.w += v.w;
        *(float4*)(ob + (size_t)i * Dm) = run;
    }
    *(float4*)&g_tot[((size_t)bh * NCH + c) * 64 + d4] = run;
}

// ---------------- K5b: Kogge-Stone inclusive scan of chunk totals ----------------
__global__ __launch_bounds__(256)
void cumsum_scan_ks()
{
    __shared__ float S[NCH * 64];   // 32 KB
    int bh = blockIdx.x, tid = threadIdx.x;
    float* gt = g_tot + (size_t)bh * (NCH * 64);

    for (int i = tid; i < NCH * 64; i += 256) S[i] = gt[i];
    __syncthreads();

    for (int off = 1; off < NCH; off <<= 1) {
        float t[32];
        #pragma unroll
        for (int j = 0; j < 32; j++) {
            int idx = tid + j * 256;
            int c = idx >> 6;
            t[j] = (c >= off) ? S[idx - (off << 6)] : 0.f;
        }
        __syncthreads();
        #pragma unroll
        for (int j = 0; j < 32; j++) S[tid + j * 256] += t[j];
        __syncthreads();
    }

    for (int i = tid; i < NCH * 64; i += 256) gt[i] = S[i];
}

// ---------------- K5c: add chunk offsets (inclusive prefix of c-1) ----------------
__global__ __launch_bounds__(128)
void cumsum_add(float* __restrict__ out)
{
    int tid = threadIdx.x;
    int c = blockIdx.x * 8 + (tid >> 4);
    if (c == 0) return;
    int bh = blockIdx.y;
    int d4 = (tid & 15) * 4;
    float4 off = *(const float4*)&g_tot[((size_t)bh * NCH + (c - 1)) * 64 + d4];
    int b = bh >> 3, h = bh & 7;
    float* ob = out + ((size_t)(b * Ln + c * 32)) * Dm + h * 64 + d4;
    #pragma unroll 8
    for (int i = 0; i < 32; i++) {
        float4 v = *(const float4*)(ob + (size_t)i * Dm);
        v.x += off.x; v.y += off.y; v.z += off.z; v.w += off.w;
        *(float4*)(ob + (size_t)i * Dm) = v;
    }
}

// ---------------- K4: full attention on selected rows + scatter ----------------
__global__ __launch_bounds__(256)
void attn_kernel(float* __restrict__ out, int S)
{
    __shared__ float qs[64];
    __shared__ float sc[Ln];
    __shared__ float red[256];
    __shared__ float vr[4][64];

    int bh = blockIdx.y, u = blockIdx.x;
    int tid = threadIdx.x;
    int lu = g_top[bh * SMAX + u];
    int nk = lu + 1;   // causal: keys 0..lu inclusive

    const float* qb = g_q + ((size_t)bh << 18) + ((size_t)lu << 6);
    if (tid < 64) qs[tid] = qb[tid];
    __syncthreads();

    int warp = tid >> 5, lane = tid & 31;
    const float* kb = g_k + ((size_t)bh << 18);
    float q0 = qs[2 * lane], q1 = qs[2 * lane + 1];
    const float scale = 0.125f;  // 1/sqrt(64)

    for (int key = warp; key < nk; key += 8) {
        float2 k2 = *(const float2*)(kb + ((size_t)key << 6) + 2 * lane);
        float p = q0 * k2.x + q1 * k2.y;
        #pragma unroll
        for (int o = 16; o; o >>= 1) p += __shfl_xor_sync(0xffffffffu, p, o);
        if (lane == 0) sc[key] = p * scale;
    }
    __syncthreads();

    float mx = -INFINITY;
    for (int i = tid; i < nk; i += 256) mx = fmaxf(mx, sc[i]);
    red[tid] = mx; __syncthreads();
    for (int o = 128; o; o >>= 1) {
        if (tid < o) red[tid] = fmaxf(red[tid], red[tid + o]);
        __syncthreads();
    }
    mx = red[0]; __syncthreads();

    float z = 0.f;
    for (int i = tid; i < nk; i += 256) {
        float e = __expf(sc[i] - mx);
        sc[i] = e;
        z += e;
    }
    red[tid] = z; __syncthreads();
    for (int o = 128; o; o >>= 1) {
        if (tid < o) red[tid] += red[tid + o];
        __syncthreads();
    }
    z = red[0]; __syncthreads();

    int g = tid >> 6, dl = tid & 63;
    const float* vb = g_v + ((size_t)bh << 18);
    float acc = 0.f;
    for (int key = g; key < nk; key += 4)
        acc += sc[key] * vb[((size_t)key << 6) + dl];
    vr[g][dl] = acc;
    __syncthreads();

    if (tid < 64) {
        float s = (vr[0][tid] + vr[1][tid]) + (vr[2][tid] + vr[3][tid]);
        int b = bh >> 3, h = bh & 7;
        out[((size_t)(b * Ln + lu)) * Dm + h * 64 + tid] = s / z;
    }
}

// ---------------- launch ----------------
extern "C" void kernel_launch(void* const* d_in, const int* in_sizes, int n_in,
                              void* d_out, int out_size)
{
    const float* queries = (const float*)d_in[0];
    const float* keys    = (const float*)d_in[1];
    const float* values  = (const float*)d_in[2];
    const float* Wq = (const float*)d_in[3];
    const float* bq = (const float*)d_in[4];
    const float* Wk = (const float*)d_in[5];
    const float* bk = (const float*)d_in[6];
    const float* Wv = (const float*)d_in[7];
    const float* bv = (const float*)d_in[8];
    const int*  idxs = (const int*)d_in[9];
    int S = in_sizes[9] / Ln;   // 45
    float* out = (float*)d_out;

    float *gq, *gk, *gv;
    cudaGetSymbolAddress((void**)&gq, g_q);
    cudaGetSymbolAddress((void**)&gk, g_k);
    cudaGetSymbolAddress((void**)&gv, g_v);

    dim3 gemmGrid(Dm / BN, (Bn * Ln) / BM);   // (4, 64)
    proj_kernel<<<gemmGrid, 256>>>(queries, Wq, bq, gq);
    proj_kernel<<<gemmGrid, 256>>>(keys,    Wk, bk, gk);
    proj_kernel<<<gemmGrid, 256>>>(values,  Wv, bv, gv);

    // cumsum of v into out (final layout)
    cumsum_part<<<dim3(16, NBH), 128>>>(out);
    cumsum_scan_ks<<<NBH, 256>>>();
    cumsum_add<<<dim3(16, NBH), 128>>>(out);

    // sparse-attention measurement + selection
    sample_score_kernel<<<(NBH * Ln) / 8, 256>>>(idxs, S);
    topk_kernel<<<NBH, 256>>>(S);

    // full attention on selected rows, scatter into out
    attn_kernel<<<dim3(S, NBH), 256>>>(out, S);
}